// round 13
// baseline (speedup 1.0000x reference)
#include <cuda_runtime.h>
#include <cuda_fp16.h>
#include <math.h>
#include <stdint.h>

#define S_LEN 4096
#define HIDDEN 2048
#define NH 16
#define NKV 4
#define HD 128

// ---------------- device-global scratch (no runtime alloc allowed) ----------
__device__ float g_Qraw[S_LEN * HIDDEN];
__device__ float g_Kraw[S_LEN * NKV * HD];
__device__ float g_Vraw[S_LEN * NKV * HD];

__device__ __half g_hsH[S_LEN * HIDDEN],   g_hsL[S_LEN * HIDDEN];
__device__ __half g_WqH[HIDDEN * HIDDEN],  g_WqL[HIDDEN * HIDDEN];
__device__ __half g_WkH[NKV * HD * HIDDEN], g_WkL[NKV * HD * HIDDEN];
__device__ __half g_WvH[NKV * HD * HIDDEN], g_WvL[NKV * HD * HIDDEN];
__device__ __half g_WoH[HIDDEN * HIDDEN],  g_WoL[HIDDEN * HIDDEN];

__device__ __half g_QnH[NH * S_LEN * HD],  g_QnL[NH * S_LEN * HD];   // [h][s][d]
__device__ __half g_KnH[NKV * S_LEN * HD], g_KnL[NKV * S_LEN * HD];  // [kv][s][d]
__device__ __half g_Vn[NKV * S_LEN * HD];                            // [kv][s][d] row-major
__device__ __half g_AOH[S_LEN * HIDDEN];                             // [s][hid] hi only

// ---------------- helpers ---------------------------------------------------
__device__ __forceinline__ void split16(float x, __half& hi, __half& lo) {
    hi = __float2half_rn(x);
    lo = __float2half_rn(x - __half2float(hi));
}
__device__ __forceinline__ void cp16(uint32_t dst, const void* src) {
    asm volatile("cp.async.cg.shared.global [%0], [%1], 16;\n" :: "r"(dst), "l"(src));
}
__device__ __forceinline__ void cp_commit() {
    asm volatile("cp.async.commit_group;\n");
}
template <int N>
__device__ __forceinline__ void cp_wait() {
    asm volatile("cp.async.wait_group %0;\n" :: "n"(N));
}
__device__ __forceinline__ void ldsm4(uint32_t* r, uint32_t a) {
    asm volatile("ldmatrix.sync.aligned.m8n8.x4.shared.b16 {%0,%1,%2,%3}, [%4];\n"
                 : "=r"(r[0]), "=r"(r[1]), "=r"(r[2]), "=r"(r[3]) : "r"(a));
}
__device__ __forceinline__ void ldsm4t(uint32_t* r, uint32_t a) {
    asm volatile("ldmatrix.sync.aligned.m8n8.x4.trans.shared.b16 {%0,%1,%2,%3}, [%4];\n"
                 : "=r"(r[0]), "=r"(r[1]), "=r"(r[2]), "=r"(r[3]) : "r"(a));
}
// fp16 m16n8k16, fp32 accum.
__device__ __forceinline__ void mma16(float* c, const uint32_t* a, const uint32_t* b) {
    asm volatile(
        "mma.sync.aligned.m16n8k16.row.col.f32.f16.f16.f32 "
        "{%0,%1,%2,%3},{%4,%5,%6,%7},{%8,%9},{%0,%1,%2,%3};\n"
        : "+f"(c[0]), "+f"(c[1]), "+f"(c[2]), "+f"(c[3])
        : "r"(a[0]), "r"(a[1]), "r"(a[2]), "r"(a[3]), "r"(b[0]), "r"(b[1]));
}
__device__ __forceinline__ uint32_t pack2(float a, float b) {
    __half2 t = __halves2half2(__float2half_rn(a), __float2half_rn(b));
    return *reinterpret_cast<uint32_t*>(&t);
}

// ---------------- fused fp32 -> fp16 hi/lo split (5 tensors, 1 launch) ------
struct SplitJob { const float* in; __half* hi; __half* lo; int n4; };

__global__ void __launch_bounds__(256) split_all_kernel(
    SplitJob j0, SplitJob j1, SplitJob j2, SplitJob j3, SplitJob j4)
{
    int i = blockIdx.x * 256 + threadIdx.x;
    const float* in; __half *hi, *lo;
    if (i < j0.n4)      { in = j0.in; hi = j0.hi; lo = j0.lo; }
    else if ((i -= j0.n4) < j1.n4) { in = j1.in; hi = j1.hi; lo = j1.lo; }
    else if ((i -= j1.n4) < j2.n4) { in = j2.in; hi = j2.hi; lo = j2.lo; }
    else if ((i -= j2.n4) < j3.n4) { in = j3.in; hi = j3.hi; lo = j3.lo; }
    else if ((i -= j3.n4) < j4.n4) { in = j4.in; hi = j4.hi; lo = j4.lo; }
    else return;
    float4 v = ((const float4*)in)[i];
    __half h0, l0, h1, l1, h2, l2, h3, l3;
    split16(v.x, h0, l0); split16(v.y, h1, l1);
    split16(v.z, h2, l2); split16(v.w, h3, l3);
    ((__half2*)hi)[2 * i]     = __halves2half2(h0, h1);
    ((__half2*)hi)[2 * i + 1] = __halves2half2(h2, h3);
    ((__half2*)lo)[2 * i]     = __halves2half2(l0, l1);
    ((__half2*)lo)[2 * i + 1] = __halves2half2(l2, l3);
}

// ---------------- fp16x3 GEMM core (score path) -----------------------------
// 3-stage cp.async, ONE barrier per k-chunk, NO forced CTA count (regs free,
// no spills). 1 CTA/SM with 123 KB smem.
#define GK 32
#define GLDH 40
#define GARR (128 * GLDH)
#define GSTAGE3 (4 * GARR)            // Ah, Al, Bh, Bl
#define GST3 3
#define GEMM3_SMEM_BYTES (GST3 * GSTAGE3 * 2)

__device__ __forceinline__ void gemm_core3(
    const __half* __restrict__ A0h, const __half* __restrict__ A0l,
    const __half* __restrict__ B0h, const __half* __restrict__ B0l,
    float* __restrict__ Cb, int N, int K)
{
    extern __shared__ __half smh[];
    uint32_t sbase = (uint32_t)__cvta_generic_to_shared(smh);
    const int tid = threadIdx.x, w = tid >> 5, lane = tid & 31;
    const int g = lane >> 2, t4 = lane & 3;
    const int wm = w >> 1, wn = w & 1;
    const int la7 = lane & 7, lb = (lane >> 3) & 1, lc = (lane >> 4) & 1;
    const uint32_t offA = ((uint32_t)(wm * 32 + la7 + lb * 8) * GLDH + lc * 8) * 2;
    const uint32_t offB = ((uint32_t)(wn * 64 + lc * 8 + la7) * GLDH + lb * 8) * 2;
    const int nch = K / GK;

    float acc[2][8][4];
#pragma unroll
    for (int mt = 0; mt < 2; mt++)
#pragma unroll
        for (int nt = 0; nt < 8; nt++)
#pragma unroll
            for (int r = 0; r < 4; r++) acc[mt][nt][r] = 0.f;

    auto issue = [&](int chunk) {
        uint32_t sb = sbase + (uint32_t)((chunk % GST3) * GSTAGE3 * 2);
        int k0 = chunk * GK;
#pragma unroll
        for (int j = 0; j < 2; j++) {
            int c = tid + j * 256;
            int row = c >> 2, seg = c & 3;
            size_t go = (size_t)row * K + k0 + seg * 8;
            uint32_t so = (uint32_t)(row * GLDH + seg * 8) * 2;
            cp16(sb + 0 * GARR * 2 + so, A0h + go);
            cp16(sb + 1 * GARR * 2 + so, A0l + go);
            cp16(sb + 2 * GARR * 2 + so, B0h + go);
            cp16(sb + 3 * GARR * 2 + so, B0l + go);
        }
    };

    issue(0); cp_commit();
    issue(1); cp_commit();

    for (int i = 0; i < nch; i++) {
        if (i + 1 < nch) cp_wait<1>(); else cp_wait<0>();
        __syncthreads();   // stage i ready AND all threads done with stage (i+2)%3
        if (i + 2 < nch) { issue(i + 2); cp_commit(); }
        uint32_t base = sbase + (uint32_t)((i % GST3) * GSTAGE3 * 2);
#pragma unroll
        for (int ks = 0; ks < 2; ks++) {
            uint32_t ah[2][4], al[2][4];
#pragma unroll
            for (int mt = 0; mt < 2; mt++) {
                uint32_t o = offA + (uint32_t)(mt * 16 * GLDH + ks * 16) * 2;
                ldsm4(ah[mt], base + o);
                ldsm4(al[mt], base + GARR * 2 + o);
            }
#pragma unroll
            for (int p = 0; p < 4; p++) {
                uint32_t bh4[4], bl4[4];
                uint32_t o = offB + (uint32_t)(p * 16 * GLDH + ks * 16) * 2;
                ldsm4(bh4, base + 2 * GARR * 2 + o);
                ldsm4(bl4, base + 3 * GARR * 2 + o);
#pragma unroll
                for (int q = 0; q < 2; q++) {
                    int nt = p * 2 + q;
                    uint32_t bh2[2] = {bh4[q * 2], bh4[q * 2 + 1]};
                    uint32_t bl2[2] = {bl4[q * 2], bl4[q * 2 + 1]};
                    mma16(acc[0][nt], ah[0], bh2);
                    mma16(acc[1][nt], ah[1], bh2);
                    mma16(acc[0][nt], ah[0], bl2);
                    mma16(acc[1][nt], ah[1], bl2);
                    mma16(acc[0][nt], al[0], bh2);
                    mma16(acc[1][nt], al[1], bh2);
                }
            }
        }
    }

#pragma unroll
    for (int mt = 0; mt < 2; mt++) {
        int r0 = wm * 32 + mt * 16 + g;
#pragma unroll
        for (int nt = 0; nt < 8; nt++) {
            int col = wn * 64 + nt * 8 + 2 * t4;
            *(float2*)&Cb[(size_t)r0 * N + col] =
                make_float2(acc[mt][nt][0], acc[mt][nt][1]);
            *(float2*)&Cb[(size_t)(r0 + 8) * N + col] =
                make_float2(acc[mt][nt][2], acc[mt][nt][3]);
        }
    }
}

// fused QKV projection: bx 0..15 -> Q, 16..19 -> K, 20..23 -> V (all x3)
__global__ void __launch_bounds__(256) qkv_gemm_kernel(
    const __half* __restrict__ hsH, const __half* __restrict__ hsL,
    const __half* __restrict__ wqH, const __half* __restrict__ wqL,
    const __half* __restrict__ wkH, const __half* __restrict__ wkL,
    const __half* __restrict__ wvH, const __half* __restrict__ wvL,
    float* __restrict__ qraw, float* __restrict__ kraw, float* __restrict__ vraw)
{
    const int bx = blockIdx.x, by = blockIdx.y;
    const __half *Bh, *Bl; float* C; int N, cx;
    if (bx < 16)      { Bh = wqH; Bl = wqL; C = qraw; N = HIDDEN;   cx = bx; }
    else if (bx < 20) { Bh = wkH; Bl = wkL; C = kraw; N = NKV * HD; cx = bx - 16; }
    else              { Bh = wvH; Bl = wvL; C = vraw; N = NKV * HD; cx = bx - 20; }
    gemm_core3(hsH + (size_t)by * 128 * HIDDEN, hsL + (size_t)by * 128 * HIDDEN,
               Bh + (size_t)cx * 128 * HIDDEN, Bl + (size_t)cx * 128 * HIDDEN,
               C + (size_t)by * 128 * N + cx * 128, N, HIDDEN);
}

// ---------------- fp16x2 GEMM (output projection; A hi-only) ----------------
#define GSTAGE2 (3 * GARR)            // Ah, Bh, Bl
#define GST2 3
#define GEMM2_SMEM_BYTES (GST2 * GSTAGE2 * 2)

__global__ void __launch_bounds__(256, 2) gemm_fp16x2(
    const __half* __restrict__ Ah,
    const __half* __restrict__ Bh, const __half* __restrict__ Bl,
    float* __restrict__ C, int M, int N, int K)
{
    extern __shared__ __half smh[];
    uint32_t sbase = (uint32_t)__cvta_generic_to_shared(smh);
    const int tid = threadIdx.x, w = tid >> 5, lane = tid & 31;
    const int g = lane >> 2, t4 = lane & 3;
    const int wm = w >> 1, wn = w & 1;
    const int la7 = lane & 7, lb = (lane >> 3) & 1, lc = (lane >> 4) & 1;
    const uint32_t offA = ((uint32_t)(wm * 32 + la7 + lb * 8) * GLDH + lc * 8) * 2;
    const uint32_t offB = ((uint32_t)(wn * 64 + lc * 8 + la7) * GLDH + lb * 8) * 2;
    const __half* A0h = Ah + (size_t)blockIdx.y * 128 * K;
    const __half* B0h = Bh + (size_t)blockIdx.x * 128 * K;
    const __half* B0l = Bl + (size_t)blockIdx.x * 128 * K;
    float* Cb = C + (size_t)blockIdx.y * 128 * N + blockIdx.x * 128;
    const int nch = K / GK;

    float acc[2][8][4];
#pragma unroll
    for (int mt = 0; mt < 2; mt++)
#pragma unroll
        for (int nt = 0; nt < 8; nt++)
#pragma unroll
            for (int r = 0; r < 4; r++) acc[mt][nt][r] = 0.f;

    auto issue = [&](int chunk) {
        uint32_t sb = sbase + (uint32_t)((chunk % GST2) * GSTAGE2 * 2);
        int k0 = chunk * GK;
#pragma unroll
        for (int j = 0; j < 2; j++) {
            int c = tid + j * 256;
            int row = c >> 2, seg = c & 3;
            size_t go = (size_t)row * K + k0 + seg * 8;
            uint32_t so = (uint32_t)(row * GLDH + seg * 8) * 2;
            cp16(sb + 0 * GARR * 2 + so, A0h + go);
            cp16(sb + 1 * GARR * 2 + so, B0h + go);
            cp16(sb + 2 * GARR * 2 + so, B0l + go);
        }
    };

    issue(0); cp_commit();
    issue(1); cp_commit();

    for (int i = 0; i < nch; i++) {
        if (i + 1 < nch) cp_wait<1>(); else cp_wait<0>();
        __syncthreads();
        if (i + 2 < nch) { issue(i + 2); cp_commit(); }
        uint32_t base = sbase + (uint32_t)((i % GST2) * GSTAGE2 * 2);
#pragma unroll
        for (int ks = 0; ks < 2; ks++) {
            uint32_t ah[2][4];
#pragma unroll
            for (int mt = 0; mt < 2; mt++) {
                uint32_t o = offA + (uint32_t)(mt * 16 * GLDH + ks * 16) * 2;
                ldsm4(ah[mt], base + o);
            }
#pragma unroll
            for (int p = 0; p < 4; p++) {
                uint32_t bh4[4], bl4[4];
                uint32_t o = offB + (uint32_t)(p * 16 * GLDH + ks * 16) * 2;
                ldsm4(bh4, base + 1 * GARR * 2 + o);
                ldsm4(bl4, base + 2 * GARR * 2 + o);
#pragma unroll
                for (int q = 0; q < 2; q++) {
                    int nt = p * 2 + q;
                    uint32_t bh2[2] = {bh4[q * 2], bh4[q * 2 + 1]};
                    uint32_t bl2[2] = {bl4[q * 2], bl4[q * 2 + 1]};
                    mma16(acc[0][nt], ah[0], bh2);
                    mma16(acc[1][nt], ah[1], bh2);
                    mma16(acc[0][nt], ah[0], bl2);
                    mma16(acc[1][nt], ah[1], bl2);
                }
            }
        }
    }

#pragma unroll
    for (int mt = 0; mt < 2; mt++) {
        int r0 = wm * 32 + mt * 16 + g;
#pragma unroll
        for (int nt = 0; nt < 8; nt++) {
            int col = wn * 64 + nt * 8 + 2 * t4;
            *(float2*)&Cb[(size_t)r0 * N + col] =
                make_float2(acc[mt][nt][0], acc[mt][nt][1]);
            *(float2*)&Cb[(size_t)(r0 + 8) * N + col] =
                make_float2(acc[mt][nt][2], acc[mt][nt][3]);
        }
    }
}

// ---------------- fused RMSNorm (+RoPE) for Q, K, V -------------------------
__device__ __forceinline__ void norm_task_rope(
    const float* __restrict__ in, __half* __restrict__ outH,
    __half* __restrict__ outL, const float* __restrict__ w,
    const float* __restrict__ cosT, const float* __restrict__ sinT,
    int nheads, int task, int lane)
{
    int s = task / nheads, hh = task - s * nheads;
    const float* x = in + (size_t)s * (nheads * HD) + hh * HD;
    float v0 = x[lane], v1 = x[lane + 32], v2 = x[lane + 64], v3 = x[lane + 96];
    float ss = v0 * v0 + v1 * v1 + v2 * v2 + v3 * v3;
#pragma unroll
    for (int o = 16; o > 0; o >>= 1) ss += __shfl_xor_sync(0xFFFFFFFFu, ss, o);
    float inv = rsqrtf(ss * (1.f / HD) + 1e-6f);
    float n0 = v0 * inv * w[lane], n1 = v1 * inv * w[lane + 32];
    float n2 = v2 * inv * w[lane + 64], n3 = v3 * inv * w[lane + 96];
    const float* c  = cosT + (size_t)s * HD;
    const float* sn = sinT + (size_t)s * HD;
    float o0 = n0 * c[lane]      - n2 * sn[lane];
    float o1 = n1 * c[lane + 32] - n3 * sn[lane + 32];
    float o2 = n2 * c[lane + 64] + n0 * sn[lane + 64];
    float o3 = n3 * c[lane + 96] + n1 * sn[lane + 96];
    __half ah, al;
    __half* yh = outH + ((size_t)hh * S_LEN + s) * HD;
    __half* yl = outL + ((size_t)hh * S_LEN + s) * HD;
    split16(o0, ah, al); yh[lane] = ah;      yl[lane] = al;
    split16(o1, ah, al); yh[lane + 32] = ah; yl[lane + 32] = al;
    split16(o2, ah, al); yh[lane + 64] = ah; yl[lane + 64] = al;
    split16(o3, ah, al); yh[lane + 96] = ah; yl[lane + 96] = al;
}

__global__ void __launch_bounds__(128) norm_all_kernel(
    const float* __restrict__ qraw, const float* __restrict__ kraw,
    const float* __restrict__ vraw,
    __half* __restrict__ qnH, __half* __restrict__ qnL,
    __half* __restrict__ knH, __half* __restrict__ knL,
    __half* __restrict__ vn,
    const float* __restrict__ qw, const float* __restrict__ kw,
    const float* __restrict__ cosT, const float* __restrict__ sinT)
{
    int t = blockIdx.x * 4 + (threadIdx.x >> 5);
    int lane = threadIdx.x & 31;
    const int NQ = S_LEN * NH, NK = S_LEN * NKV;
    if (t < NQ) {
        norm_task_rope(qraw, qnH, qnL, qw, cosT, sinT, NH, t, lane);
    } else if ((t -= NQ) < NK) {
        norm_task_rope(kraw, knH, knL, kw, cosT, sinT, NKV, t, lane);
    } else if ((t -= NK) < NK) {
        int s = t / NKV, hh = t - s * NKV;
        const float* x = vraw + (size_t)s * (NKV * HD) + hh * HD;
        float v0 = x[lane], v1 = x[lane + 32], v2 = x[lane + 64], v3 = x[lane + 96];
        float ss = v0 * v0 + v1 * v1 + v2 * v2 + v3 * v3;
#pragma unroll
        for (int o = 16; o > 0; o >>= 1) ss += __shfl_xor_sync(0xFFFFFFFFu, ss, o);
        float inv = rsqrtf(ss * (1.f / HD) + 1e-6f);
        __half* y = vn + ((size_t)hh * S_LEN + s) * HD;   // row-major, coalesced
        y[lane]      = __float2half_rn(v0 * inv);
        y[lane + 32] = __float2half_rn(v1 * inv);
        y[lane + 64] = __float2half_rn(v2 * inv);
        y[lane + 96] = __float2half_rn(v3 * inv);
    }
}

// ---------------- causal GQA flash attention, fp16 MMA (round-11 exact) -----
#define ALDQ 136
#define OFF_QH 0
#define OFF_QL (128 * ALDQ)
#define OFF_KH0 (2 * 128 * ALDQ)
#define OFF_KL0 (OFF_KH0 + 64 * ALDQ)
#define OFF_KH1 (OFF_KL0 + 64 * ALDQ)
#define OFF_KL1 (OFF_KH1 + 64 * ALDQ)
#define OFF_VS0 (OFF_KL1 + 64 * ALDQ)
#define OFF_VS1 (OFF_VS0 + 64 * ALDQ)
#define HALVES_TOT (OFF_VS1 + 64 * ALDQ)
#define ATTN_SMEM_BYTES (HALVES_TOT * 2)

__global__ void __launch_bounds__(256) attn_fp16_kernel(
    const __half* __restrict__ Qh_g, const __half* __restrict__ Ql_g,
    const __half* __restrict__ Kh_g, const __half* __restrict__ Kl_g,
    const __half* __restrict__ V_g,
    __half* __restrict__ AOh)
{
    extern __shared__ __half sm[];
    __half* Qh = sm + OFF_QH;
    __half* Ql = sm + OFF_QL;
    uint32_t su = (uint32_t)__cvta_generic_to_shared(sm);
    const uint32_t uKH[2] = {su + OFF_KH0 * 2, su + OFF_KH1 * 2};
    const uint32_t uKL[2] = {su + OFF_KL0 * 2, su + OFF_KL1 * 2};
    const uint32_t uVS[2] = {su + OFF_VS0 * 2, su + OFF_VS1 * 2};

    const int hq = blockIdx.x;
    const int rb = (gridDim.y - 1) - blockIdx.y;   // heavy blocks first
    const int kvh = hq >> 2;
    const int tid = threadIdx.x, w = tid >> 5, lane = tid & 31;
    const int g = lane >> 2, t4 = lane & 3;
    const int m0 = 16 * w;
    const int la7 = lane & 7, lb = (lane >> 3) & 1, lc = (lane >> 4) & 1;

    const uint32_t offQA = ((uint32_t)(m0 + la7 + lb * 8) * ALDQ + lc * 8) * 2;
    const uint32_t offKB = ((uint32_t)(lc * 8 + la7) * ALDQ + lb * 8) * 2;
    const uint32_t offVB = ((uint32_t)(lb * 8 + la7) * ALDQ + lc * 8) * 2;

    const __half* Qg_h = Qh_g + ((size_t)hq * S_LEN + rb * 128) * HD;
    const __half* Qg_l = Ql_g + ((size_t)hq * S_LEN + rb * 128) * HD;
    const __half* Kg_h = Kh_g + (size_t)kvh * S_LEN * HD;
    const __half* Kg_l = Kl_g + (size_t)kvh * S_LEN * HD;
    const __half* Vg   = V_g  + (size_t)kvh * S_LEN * HD;

    auto issueKV = [&](int kb) {
        int st = kb & 1;
#pragma unroll
        for (int j = 0; j < 4; j++) {
            int c = tid + j * 256;            // 0..1023
            int row = c >> 4, seg = c & 15;
            size_t go = (size_t)(kb * 64 + row) * HD + seg * 8;
            uint32_t so = (uint32_t)(row * ALDQ + seg * 8) * 2;
            cp16(uKH[st] + so, Kg_h + go);
            cp16(uKL[st] + so, Kg_l + go);
            cp16(uVS[st] + so, Vg + go);
        }
    };

    issueKV(0); cp_commit();

    // Q tiles hi/lo (plain loads, overlap with cp.async)
#pragma unroll
    for (int j = 0; j < 8; j++) {
        int c = tid + j * 256;
        int row = c >> 4, seg = c & 15;
        *(uint4*)&Qh[row * ALDQ + seg * 8] =
            *(const uint4*)(Qg_h + (size_t)row * HD + seg * 8);
        *(uint4*)&Ql[row * ALDQ + seg * 8] =
            *(const uint4*)(Qg_l + (size_t)row * HD + seg * 8);
    }

    float mL = -INFINITY, mH = -INFINITY, lLs = 0.f, lHs = 0.f;
    float oacc[16][4];
#pragma unroll
    for (int nt = 0; nt < 16; nt++)
#pragma unroll
        for (int r = 0; r < 4; r++) oacc[nt][r] = 0.f;

    const int kbmax = 2 * rb + 1;
    for (int kb = 0; kb <= kbmax; kb++) {
        const int st = kb & 1;
        cp_wait<0>();
        __syncthreads();   // tile kb resident; all warps done reading st^1
        if (kb + 1 <= kbmax) { issueKV(kb + 1); cp_commit(); }

        // warps whose rows are entirely above the diagonal tile: skip
        if (kb == kbmax && m0 + 15 < 64) continue;

        // ---- S = Q K^T (fp16x3): 16 rows x 64 cols per warp ----
        float sacc[8][4];
#pragma unroll
        for (int nt = 0; nt < 8; nt++)
#pragma unroll
            for (int r = 0; r < 4; r++) sacc[nt][r] = 0.f;

#pragma unroll
        for (int ks = 0; ks < 8; ks++) {
            uint32_t ah[4], al[4];
            uint32_t oq = offQA + (uint32_t)(ks * 16) * 2;
            ldsm4(ah, su + OFF_QH * 2 + oq);
            ldsm4(al, su + OFF_QL * 2 + oq);
#pragma unroll
            for (int p = 0; p < 4; p++) {
                uint32_t bh4[4], bl4[4];
                uint32_t o = offKB + (uint32_t)(p * 16 * ALDQ + ks * 16) * 2;
                ldsm4(bh4, uKH[st] + o);
                ldsm4(bl4, uKL[st] + o);
#pragma unroll
                for (int q = 0; q < 2; q++) {
                    int nt = p * 2 + q;
                    uint32_t bh2[2] = {bh4[q * 2], bh4[q * 2 + 1]};
                    uint32_t bl2[2] = {bl4[q * 2], bl4[q * 2 + 1]};
                    mma16(sacc[nt], ah, bh2);
                    mma16(sacc[nt], ah, bl2);
                    mma16(sacc[nt], al, bh2);
                }
            }
        }

        // ---- causal mask ----
        if (kb >= 2 * rb) {
            int r0 = rb * 128 + m0 + g, r1 = r0 + 8;
#pragma unroll
            for (int nt = 0; nt < 8; nt++) {
                int c0 = kb * 64 + nt * 8 + 2 * t4;
                if (c0 > r0)     sacc[nt][0] = -INFINITY;
                if (c0 + 1 > r0) sacc[nt][1] = -INFINITY;
                if (c0 > r1)     sacc[nt][2] = -INFINITY;
                if (c0 + 1 > r1) sacc[nt][3] = -INFINITY;
            }
        }

        // ---- warp-local online softmax ----
        float rmL = -INFINITY, rmH = -INFINITY;
#pragma unroll
        for (int nt = 0; nt < 8; nt++) {
            rmL = fmaxf(rmL, fmaxf(sacc[nt][0], sacc[nt][1]));
            rmH = fmaxf(rmH, fmaxf(sacc[nt][2], sacc[nt][3]));
        }
        rmL = fmaxf(rmL, __shfl_xor_sync(0xFFFFFFFFu, rmL, 1));
        rmL = fmaxf(rmL, __shfl_xor_sync(0xFFFFFFFFu, rmL, 2));
        rmH = fmaxf(rmH, __shfl_xor_sync(0xFFFFFFFFu, rmH, 1));
        rmH = fmaxf(rmH, __shfl_xor_sync(0xFFFFFFFFu, rmH, 2));
        float mnL = fmaxf(mL, rmL), mnH = fmaxf(mH, rmH);
        float aL = __expf(mL - mnL), aH = __expf(mH - mnH);
        mL = mnL; mH = mnH;

        uint32_t pfL[8], pfH[8];
        float lsL = 0.f, lsH = 0.f;
#pragma unroll
        for (int nt = 0; nt < 8; nt++) {
            float p0 = __expf(sacc[nt][0] - mnL);
            float p1 = __expf(sacc[nt][1] - mnL);
            float p2 = __expf(sacc[nt][2] - mnH);
            float p3 = __expf(sacc[nt][3] - mnH);
            lsL += p0 + p1; lsH += p2 + p3;
            pfL[nt] = pack2(p0, p1);
            pfH[nt] = pack2(p2, p3);
        }
        lsL += __shfl_xor_sync(0xFFFFFFFFu, lsL, 1);
        lsL += __shfl_xor_sync(0xFFFFFFFFu, lsL, 2);
        lsH += __shfl_xor_sync(0xFFFFFFFFu, lsH, 1);
        lsH += __shfl_xor_sync(0xFFFFFFFFu, lsH, 2);
        lLs = lLs * aL + lsL;
        lHs = lHs * aH + lsH;

#pragma unroll
        for (int nt = 0; nt < 16; nt++) {
            oacc[nt][0] *= aL; oacc[nt][1] *= aL;
            oacc[nt][2] *= aH; oacc[nt][3] *= aH;
        }

        // ---- O += P @ V (P from registers; V row-major via ldsm.trans) ----
#pragma unroll
        for (int ks = 0; ks < 4; ks++) {
            uint32_t pa[4] = {pfL[2 * ks], pfH[2 * ks], pfL[2 * ks + 1], pfH[2 * ks + 1]};
#pragma unroll
            for (int p = 0; p < 8; p++) {
                uint32_t vb4[4];
                uint32_t o = offVB + (uint32_t)(ks * 16 * ALDQ + p * 16) * 2;
                ldsm4t(vb4, uVS[st] + o);
                uint32_t b0[2] = {vb4[0], vb4[1]};
                uint32_t b1[2] = {vb4[2], vb4[3]};
                mma16(oacc[2 * p],     pa, b0);
                mma16(oacc[2 * p + 1], pa, b1);
            }
        }
    }

    // ---- epilogue: normalize, fp16 convert (hi only), store AO [s][hid] ----
    float invL = 1.f / lLs, invH = 1.f / lHs;
    size_t sL = (size_t)(rb * 128 + m0 + g) * HIDDEN;
    size_t sH = (size_t)(rb * 128 + m0 + g + 8) * HIDDEN;
#pragma unroll
    for (int nt = 0; nt < 16; nt++) {
        int col = hq * HD + nt * 8 + 2 * t4;
        *(__half2*)&AOh[sL + col] = __halves2half2(
            __float2half_rn(oacc[nt][0] * invL), __float2half_rn(oacc[nt][1] * invL));
        *(__half2*)&AOh[sH + col] = __halves2half2(
            __float2half_rn(oacc[nt][2] * invH), __float2half_rn(oacc[nt][3] * invH));
    }
}

// ---------------------------------------------------------------------------
extern "C" void kernel_launch(void* const* d_in, const int* in_sizes, int n_in,
                              void* d_out, int out_size)
{
    const float* hs   = (const float*)d_in[0];
    const float* cosT = (const float*)d_in[1];
    const float* sinT = (const float*)d_in[2];
    // d_in[3] = attention_mask: pure causal, implemented directly (not read)
    const float* Wq = (const float*)d_in[4];
    const float* Wk = (const float*)d_in[5];
    const float* Wv = (const float*)d_in[6];
    const float* Wo = (const float*)d_in[7];
    const float* qw = (const float*)d_in[8];
    const float* kw = (const float*)d_in[9];
    float* out = (float*)d_out;

    float *qraw, *kraw, *vraw;
    __half *hsH, *hsL, *wqH, *wqL, *wkH, *wkL, *wvH, *wvL, *woH, *woL;
    __half *qnH, *qnL, *knH, *knL, *vn, *aoH;
    cudaGetSymbolAddress((void**)&qraw, g_Qraw);
    cudaGetSymbolAddress((void**)&kraw, g_Kraw);
    cudaGetSymbolAddress((void**)&vraw, g_Vraw);
    cudaGetSymbolAddress((void**)&hsH, g_hsH); cudaGetSymbolAddress((void**)&hsL, g_hsL);
    cudaGetSymbolAddress((void**)&wqH, g_WqH); cudaGetSymbolAddress((void**)&wqL, g_WqL);
    cudaGetSymbolAddress((void**)&wkH, g_WkH); cudaGetSymbolAddress((void**)&wkL, g_WkL);
    cudaGetSymbolAddress((void**)&wvH, g_WvH); cudaGetSymbolAddress((void**)&wvL, g_WvL);
    cudaGetSymbolAddress((void**)&woH, g_WoH); cudaGetSymbolAddress((void**)&woL, g_WoL);
    cudaGetSymbolAddress((void**)&qnH, g_QnH); cudaGetSymbolAddress((void**)&qnL, g_QnL);
    cudaGetSymbolAddress((void**)&knH, g_KnH); cudaGetSymbolAddress((void**)&knL, g_KnL);
    cudaGetSymbolAddress((void**)&vn, g_Vn);
    cudaGetSymbolAddress((void**)&aoH, g_AOH);

    cudaFuncSetAttribute(qkv_gemm_kernel,
                         cudaFuncAttributeMaxDynamicSharedMemorySize, GEMM3_SMEM_BYTES);
    cudaFuncSetAttribute(gemm_fp16x2,
                         cudaFuncAttributeMaxDynamicSharedMemorySize, GEMM2_SMEM_BYTES);
    cudaFuncSetAttribute(attn_fp16_kernel,
                         cudaFuncAttributeMaxDynamicSharedMemorySize, ATTN_SMEM_BYTES);

    // split inputs to fp16 hi/lo (single fused launch)
    {
        SplitJob j0 = {hs, hsH, hsL, S_LEN * HIDDEN / 4};
        SplitJob j1 = {Wq, wqH, wqL, HIDDEN * HIDDEN / 4};
        SplitJob j2 = {Wk, wkH, wkL, NKV * HD * HIDDEN / 4};
        SplitJob j3 = {Wv, wvH, wvL, NKV * HD * HIDDEN / 4};
        SplitJob j4 = {Wo, woH, woL, HIDDEN * HIDDEN / 4};
        int tot = j0.n4 + j1.n4 + j2.n4 + j3.n4 + j4.n4;
        split_all_kernel<<<(tot + 255) / 256, 256>>>(j0, j1, j2, j3, j4);
    }

    // fused QKV projections (fp16x3, 3-stage, unbounded regs)
    qkv_gemm_kernel<<<dim3(24, S_LEN / 128), 256, GEMM3_SMEM_BYTES>>>(
        hsH, hsL, wqH, wqL, wkH, wkL, wvH, wvL, qraw, kraw, vraw);

    // fused RMSNorm (+RoPE): Q hi/lo, K hi/lo, V row-major fp16
    {
        int tasks = S_LEN * (NH + NKV + NKV);
        norm_all_kernel<<<(tasks + 3) / 4, 128>>>(
            qraw, kraw, vraw, qnH, qnL, knH, knL, vn, qw, kw, cosT, sinT);
    }

    // attention (round-11 structure, unchanged)
    attn_fp16_kernel<<<dim3(NH, S_LEN / 128), 256, ATTN_SMEM_BYTES>>>(
        qnH, qnL, knH, knL, vn, aoH);

    // output projection (fp16x2: A = attention output hi-only)
    gemm_fp16x2<<<dim3(HIDDEN / 128, S_LEN / 128), 256, GEMM2_SMEM_BYTES>>>(
        aoH, woH, woL, out, S_LEN, HIDDEN, HIDDEN);
}

// round 14
// speedup vs baseline: 1.1065x; 1.1065x over previous
#include <cuda_runtime.h>
#include <cuda_fp16.h>
#include <math.h>
#include <stdint.h>

#define S_LEN 4096
#define HIDDEN 2048
#define NH 16
#define NKV 4
#define HD 128

// ---------------- device-global scratch (no runtime alloc allowed) ----------
__device__ float g_Qraw[S_LEN * HIDDEN];
__device__ float g_Kraw[S_LEN * NKV * HD];
__device__ float g_Vraw[S_LEN * NKV * HD];

__device__ __half g_hsH[S_LEN * HIDDEN],   g_hsL[S_LEN * HIDDEN];
__device__ __half g_WqH[HIDDEN * HIDDEN],  g_WqL[HIDDEN * HIDDEN];
__device__ __half g_WkH[NKV * HD * HIDDEN], g_WkL[NKV * HD * HIDDEN];
__device__ __half g_WvH[NKV * HD * HIDDEN], g_WvL[NKV * HD * HIDDEN];
__device__ __half g_WoH[HIDDEN * HIDDEN],  g_WoL[HIDDEN * HIDDEN];

__device__ __half g_QnH[NH * S_LEN * HD],  g_QnL[NH * S_LEN * HD];   // [h][s][d]
__device__ __half g_KnH[NKV * S_LEN * HD], g_KnL[NKV * S_LEN * HD];  // [kv][s][d]
__device__ __half g_Vn[NKV * S_LEN * HD];                            // [kv][s][d] row-major
__device__ __half g_AOH[S_LEN * HIDDEN];                             // [s][hid] hi only

// ---------------- helpers ---------------------------------------------------
__device__ __forceinline__ void split16(float x, __half& hi, __half& lo) {
    hi = __float2half_rn(x);
    lo = __float2half_rn(x - __half2float(hi));
}
__device__ __forceinline__ void cp16(uint32_t dst, const void* src) {
    asm volatile("cp.async.cg.shared.global [%0], [%1], 16;\n" :: "r"(dst), "l"(src));
}
__device__ __forceinline__ void cp_commit() {
    asm volatile("cp.async.commit_group;\n");
}
template <int N>
__device__ __forceinline__ void cp_wait() {
    asm volatile("cp.async.wait_group %0;\n" :: "n"(N));
}
__device__ __forceinline__ void ldsm4(uint32_t* r, uint32_t a) {
    asm volatile("ldmatrix.sync.aligned.m8n8.x4.shared.b16 {%0,%1,%2,%3}, [%4];\n"
                 : "=r"(r[0]), "=r"(r[1]), "=r"(r[2]), "=r"(r[3]) : "r"(a));
}
__device__ __forceinline__ void ldsm4t(uint32_t* r, uint32_t a) {
    asm volatile("ldmatrix.sync.aligned.m8n8.x4.trans.shared.b16 {%0,%1,%2,%3}, [%4];\n"
                 : "=r"(r[0]), "=r"(r[1]), "=r"(r[2]), "=r"(r[3]) : "r"(a));
}
// fp16 m16n8k16, fp32 accum.
__device__ __forceinline__ void mma16(float* c, const uint32_t* a, const uint32_t* b) {
    asm volatile(
        "mma.sync.aligned.m16n8k16.row.col.f32.f16.f16.f32 "
        "{%0,%1,%2,%3},{%4,%5,%6,%7},{%8,%9},{%0,%1,%2,%3};\n"
        : "+f"(c[0]), "+f"(c[1]), "+f"(c[2]), "+f"(c[3])
        : "r"(a[0]), "r"(a[1]), "r"(a[2]), "r"(a[3]), "r"(b[0]), "r"(b[1]));
}
__device__ __forceinline__ uint32_t pack2(float a, float b) {
    __half2 t = __halves2half2(__float2half_rn(a), __float2half_rn(b));
    return *reinterpret_cast<uint32_t*>(&t);
}

// ---------------- fused fp32 -> fp16 hi/lo split (5 tensors, 1 launch) ------
struct SplitJob { const float* in; __half* hi; __half* lo; int n4; };

__global__ void __launch_bounds__(256) split_all_kernel(
    SplitJob j0, SplitJob j1, SplitJob j2, SplitJob j3, SplitJob j4)
{
    int i = blockIdx.x * 256 + threadIdx.x;
    const float* in; __half *hi, *lo;
    if (i < j0.n4)      { in = j0.in; hi = j0.hi; lo = j0.lo; }
    else if ((i -= j0.n4) < j1.n4) { in = j1.in; hi = j1.hi; lo = j1.lo; }
    else if ((i -= j1.n4) < j2.n4) { in = j2.in; hi = j2.hi; lo = j2.lo; }
    else if ((i -= j2.n4) < j3.n4) { in = j3.in; hi = j3.hi; lo = j3.lo; }
    else if ((i -= j3.n4) < j4.n4) { in = j4.in; hi = j4.hi; lo = j4.lo; }
    else return;
    float4 v = ((const float4*)in)[i];
    __half h0, l0, h1, l1, h2, l2, h3, l3;
    split16(v.x, h0, l0); split16(v.y, h1, l1);
    split16(v.z, h2, l2); split16(v.w, h3, l3);
    ((__half2*)hi)[2 * i]     = __halves2half2(h0, h1);
    ((__half2*)hi)[2 * i + 1] = __halves2half2(h2, h3);
    ((__half2*)lo)[2 * i]     = __halves2half2(l0, l1);
    ((__half2*)lo)[2 * i + 1] = __halves2half2(l2, l3);
}

// ---------------- fp16 GEMM core (round-11 config: 2-stage, 2 CTAs/SM) ------
// USE_AL=true: x3 (Ah*Bh + Ah*Bl + Al*Bh).  USE_AL=false: x2 (drop Al term).
#define GK 32
#define GLDH 40
#define GARR (128 * GLDH)
#define GSTAGE3 (4 * GARR)            // Ah, Al, Bh, Bl
#define GEMM3_SMEM_BYTES (2 * GSTAGE3 * 2)

template <bool USE_AL>
__device__ __forceinline__ void gemm_core3(
    const __half* __restrict__ A0h, const __half* __restrict__ A0l,
    const __half* __restrict__ B0h, const __half* __restrict__ B0l,
    float* __restrict__ Cb, int N, int K)
{
    extern __shared__ __half smh[];
    uint32_t sbase = (uint32_t)__cvta_generic_to_shared(smh);
    const int tid = threadIdx.x, w = tid >> 5, lane = tid & 31;
    const int g = lane >> 2, t4 = lane & 3;
    const int wm = w >> 1, wn = w & 1;
    const int la7 = lane & 7, lb = (lane >> 3) & 1, lc = (lane >> 4) & 1;
    const uint32_t offA = ((uint32_t)(wm * 32 + la7 + lb * 8) * GLDH + lc * 8) * 2;
    const uint32_t offB = ((uint32_t)(wn * 64 + lc * 8 + la7) * GLDH + lb * 8) * 2;
    const int nch = K / GK;

    float acc[2][8][4];
#pragma unroll
    for (int mt = 0; mt < 2; mt++)
#pragma unroll
        for (int nt = 0; nt < 8; nt++)
#pragma unroll
            for (int r = 0; r < 4; r++) acc[mt][nt][r] = 0.f;

    auto issue = [&](int chunk) {
        uint32_t sb = sbase + (uint32_t)((chunk & 1) * GSTAGE3 * 2);
        int k0 = chunk * GK;
#pragma unroll
        for (int j = 0; j < 2; j++) {
            int c = tid + j * 256;
            int row = c >> 2, seg = c & 3;
            size_t go = (size_t)row * K + k0 + seg * 8;
            uint32_t so = (uint32_t)(row * GLDH + seg * 8) * 2;
            cp16(sb + 0 * GARR * 2 + so, A0h + go);
            if (USE_AL) cp16(sb + 1 * GARR * 2 + so, A0l + go);
            cp16(sb + 2 * GARR * 2 + so, B0h + go);
            cp16(sb + 3 * GARR * 2 + so, B0l + go);
        }
    };

    issue(0); cp_commit();

    for (int i = 0; i < nch; i++) {
        if (i + 1 < nch) { issue(i + 1); cp_commit(); cp_wait<1>(); }
        else             { cp_wait<0>(); }
        __syncthreads();
        uint32_t base = sbase + (uint32_t)((i & 1) * GSTAGE3 * 2);
#pragma unroll
        for (int ks = 0; ks < 2; ks++) {
            uint32_t ah[2][4], al[2][4];
#pragma unroll
            for (int mt = 0; mt < 2; mt++) {
                uint32_t o = offA + (uint32_t)(mt * 16 * GLDH + ks * 16) * 2;
                ldsm4(ah[mt], base + o);
                if (USE_AL) ldsm4(al[mt], base + GARR * 2 + o);
            }
#pragma unroll
            for (int p = 0; p < 4; p++) {
                uint32_t bh4[4], bl4[4];
                uint32_t o = offB + (uint32_t)(p * 16 * GLDH + ks * 16) * 2;
                ldsm4(bh4, base + 2 * GARR * 2 + o);
                ldsm4(bl4, base + 3 * GARR * 2 + o);
#pragma unroll
                for (int q = 0; q < 2; q++) {
                    int nt = p * 2 + q;
                    uint32_t bh2[2] = {bh4[q * 2], bh4[q * 2 + 1]};
                    uint32_t bl2[2] = {bl4[q * 2], bl4[q * 2 + 1]};
                    mma16(acc[0][nt], ah[0], bh2);
                    mma16(acc[1][nt], ah[1], bh2);
                    mma16(acc[0][nt], ah[0], bl2);
                    mma16(acc[1][nt], ah[1], bl2);
                    if (USE_AL) {
                        mma16(acc[0][nt], al[0], bh2);
                        mma16(acc[1][nt], al[1], bh2);
                    }
                }
            }
        }
        __syncthreads();
    }

#pragma unroll
    for (int mt = 0; mt < 2; mt++) {
        int r0 = wm * 32 + mt * 16 + g;
#pragma unroll
        for (int nt = 0; nt < 8; nt++) {
            int col = wn * 64 + nt * 8 + 2 * t4;
            *(float2*)&Cb[(size_t)r0 * N + col] =
                make_float2(acc[mt][nt][0], acc[mt][nt][1]);
            *(float2*)&Cb[(size_t)(r0 + 8) * N + col] =
                make_float2(acc[mt][nt][2], acc[mt][nt][3]);
        }
    }
}

// fused QKV projection: bx 0..15 -> Q (x3), 16..19 -> K (x3), 20..23 -> V (x2)
__global__ void __launch_bounds__(256, 2) qkv_gemm_kernel(
    const __half* __restrict__ hsH, const __half* __restrict__ hsL,
    const __half* __restrict__ wqH, const __half* __restrict__ wqL,
    const __half* __restrict__ wkH, const __half* __restrict__ wkL,
    const __half* __restrict__ wvH, const __half* __restrict__ wvL,
    float* __restrict__ qraw, float* __restrict__ kraw, float* __restrict__ vraw)
{
    const int bx = blockIdx.x, by = blockIdx.y;
    const __half* Ah = hsH + (size_t)by * 128 * HIDDEN;
    const __half* Al = hsL + (size_t)by * 128 * HIDDEN;
    if (bx < 16) {
        gemm_core3<true>(Ah, Al,
                         wqH + (size_t)bx * 128 * HIDDEN, wqL + (size_t)bx * 128 * HIDDEN,
                         qraw + (size_t)by * 128 * HIDDEN + bx * 128, HIDDEN, HIDDEN);
    } else if (bx < 20) {
        int cx = bx - 16;
        gemm_core3<true>(Ah, Al,
                         wkH + (size_t)cx * 128 * HIDDEN, wkL + (size_t)cx * 128 * HIDDEN,
                         kraw + (size_t)by * 128 * (NKV * HD) + cx * 128, NKV * HD, HIDDEN);
    } else {
        int cx = bx - 20;
        // V path: x2 (output is fp16-quantized downstream; lo term subdominant)
        gemm_core3<false>(Ah, Al,
                          wvH + (size_t)cx * 128 * HIDDEN, wvL + (size_t)cx * 128 * HIDDEN,
                          vraw + (size_t)by * 128 * (NKV * HD) + cx * 128, NKV * HD, HIDDEN);
    }
}

// ---------------- fp16x2 GEMM (output projection; A hi-only) ----------------
#define GSTAGE2 (3 * GARR)            // Ah, Bh, Bl
#define GST2 3
#define GEMM2_SMEM_BYTES (GST2 * GSTAGE2 * 2)

__global__ void __launch_bounds__(256, 2) gemm_fp16x2(
    const __half* __restrict__ Ah,
    const __half* __restrict__ Bh, const __half* __restrict__ Bl,
    float* __restrict__ C, int M, int N, int K)
{
    extern __shared__ __half smh[];
    uint32_t sbase = (uint32_t)__cvta_generic_to_shared(smh);
    const int tid = threadIdx.x, w = tid >> 5, lane = tid & 31;
    const int g = lane >> 2, t4 = lane & 3;
    const int wm = w >> 1, wn = w & 1;
    const int la7 = lane & 7, lb = (lane >> 3) & 1, lc = (lane >> 4) & 1;
    const uint32_t offA = ((uint32_t)(wm * 32 + la7 + lb * 8) * GLDH + lc * 8) * 2;
    const uint32_t offB = ((uint32_t)(wn * 64 + lc * 8 + la7) * GLDH + lb * 8) * 2;
    const __half* A0h = Ah + (size_t)blockIdx.y * 128 * K;
    const __half* B0h = Bh + (size_t)blockIdx.x * 128 * K;
    const __half* B0l = Bl + (size_t)blockIdx.x * 128 * K;
    float* Cb = C + (size_t)blockIdx.y * 128 * N + blockIdx.x * 128;
    const int nch = K / GK;

    float acc[2][8][4];
#pragma unroll
    for (int mt = 0; mt < 2; mt++)
#pragma unroll
        for (int nt = 0; nt < 8; nt++)
#pragma unroll
            for (int r = 0; r < 4; r++) acc[mt][nt][r] = 0.f;

    auto issue = [&](int chunk) {
        uint32_t sb = sbase + (uint32_t)((chunk % GST2) * GSTAGE2 * 2);
        int k0 = chunk * GK;
#pragma unroll
        for (int j = 0; j < 2; j++) {
            int c = tid + j * 256;
            int row = c >> 2, seg = c & 3;
            size_t go = (size_t)row * K + k0 + seg * 8;
            uint32_t so = (uint32_t)(row * GLDH + seg * 8) * 2;
            cp16(sb + 0 * GARR * 2 + so, A0h + go);
            cp16(sb + 1 * GARR * 2 + so, B0h + go);
            cp16(sb + 2 * GARR * 2 + so, B0l + go);
        }
    };

    issue(0); cp_commit();
    issue(1); cp_commit();

    for (int i = 0; i < nch; i++) {
        if (i + 1 < nch) cp_wait<1>(); else cp_wait<0>();
        __syncthreads();
        if (i + 2 < nch) { issue(i + 2); cp_commit(); }
        uint32_t base = sbase + (uint32_t)((i % GST2) * GSTAGE2 * 2);
#pragma unroll
        for (int ks = 0; ks < 2; ks++) {
            uint32_t ah[2][4];
#pragma unroll
            for (int mt = 0; mt < 2; mt++) {
                uint32_t o = offA + (uint32_t)(mt * 16 * GLDH + ks * 16) * 2;
                ldsm4(ah[mt], base + o);
            }
#pragma unroll
            for (int p = 0; p < 4; p++) {
                uint32_t bh4[4], bl4[4];
                uint32_t o = offB + (uint32_t)(p * 16 * GLDH + ks * 16) * 2;
                ldsm4(bh4, base + 1 * GARR * 2 + o);
                ldsm4(bl4, base + 2 * GARR * 2 + o);
#pragma unroll
                for (int q = 0; q < 2; q++) {
                    int nt = p * 2 + q;
                    uint32_t bh2[2] = {bh4[q * 2], bh4[q * 2 + 1]};
                    uint32_t bl2[2] = {bl4[q * 2], bl4[q * 2 + 1]};
                    mma16(acc[0][nt], ah[0], bh2);
                    mma16(acc[1][nt], ah[1], bh2);
                    mma16(acc[0][nt], ah[0], bl2);
                    mma16(acc[1][nt], ah[1], bl2);
                }
            }
        }
    }

#pragma unroll
    for (int mt = 0; mt < 2; mt++) {
        int r0 = wm * 32 + mt * 16 + g;
#pragma unroll
        for (int nt = 0; nt < 8; nt++) {
            int col = wn * 64 + nt * 8 + 2 * t4;
            *(float2*)&Cb[(size_t)r0 * N + col] =
                make_float2(acc[mt][nt][0], acc[mt][nt][1]);
            *(float2*)&Cb[(size_t)(r0 + 8) * N + col] =
                make_float2(acc[mt][nt][2], acc[mt][nt][3]);
        }
    }
}

// ---------------- fused RMSNorm (+RoPE) for Q, K, V -------------------------
__device__ __forceinline__ void norm_task_rope(
    const float* __restrict__ in, __half* __restrict__ outH,
    __half* __restrict__ outL, const float* __restrict__ w,
    const float* __restrict__ cosT, const float* __restrict__ sinT,
    int nheads, int task, int lane)
{
    int s = task / nheads, hh = task - s * nheads;
    const float* x = in + (size_t)s * (nheads * HD) + hh * HD;
    float v0 = x[lane], v1 = x[lane + 32], v2 = x[lane + 64], v3 = x[lane + 96];
    float ss = v0 * v0 + v1 * v1 + v2 * v2 + v3 * v3;
#pragma unroll
    for (int o = 16; o > 0; o >>= 1) ss += __shfl_xor_sync(0xFFFFFFFFu, ss, o);
    float inv = rsqrtf(ss * (1.f / HD) + 1e-6f);
    float n0 = v0 * inv * w[lane], n1 = v1 * inv * w[lane + 32];
    float n2 = v2 * inv * w[lane + 64], n3 = v3 * inv * w[lane + 96];
    const float* c  = cosT + (size_t)s * HD;
    const float* sn = sinT + (size_t)s * HD;
    float o0 = n0 * c[lane]      - n2 * sn[lane];
    float o1 = n1 * c[lane + 32] - n3 * sn[lane + 32];
    float o2 = n2 * c[lane + 64] + n0 * sn[lane + 64];
    float o3 = n3 * c[lane + 96] + n1 * sn[lane + 96];
    __half ah, al;
    __half* yh = outH + ((size_t)hh * S_LEN + s) * HD;
    __half* yl = outL + ((size_t)hh * S_LEN + s) * HD;
    split16(o0, ah, al); yh[lane] = ah;      yl[lane] = al;
    split16(o1, ah, al); yh[lane + 32] = ah; yl[lane + 32] = al;
    split16(o2, ah, al); yh[lane + 64] = ah; yl[lane + 64] = al;
    split16(o3, ah, al); yh[lane + 96] = ah; yl[lane + 96] = al;
}

__global__ void __launch_bounds__(128) norm_all_kernel(
    const float* __restrict__ qraw, const float* __restrict__ kraw,
    const float* __restrict__ vraw,
    __half* __restrict__ qnH, __half* __restrict__ qnL,
    __half* __restrict__ knH, __half* __restrict__ knL,
    __half* __restrict__ vn,
    const float* __restrict__ qw, const float* __restrict__ kw,
    const float* __restrict__ cosT, const float* __restrict__ sinT)
{
    int t = blockIdx.x * 4 + (threadIdx.x >> 5);
    int lane = threadIdx.x & 31;
    const int NQ = S_LEN * NH, NK = S_LEN * NKV;
    if (t < NQ) {
        norm_task_rope(qraw, qnH, qnL, qw, cosT, sinT, NH, t, lane);
    } else if ((t -= NQ) < NK) {
        norm_task_rope(kraw, knH, knL, kw, cosT, sinT, NKV, t, lane);
    } else if ((t -= NK) < NK) {
        int s = t / NKV, hh = t - s * NKV;
        const float* x = vraw + (size_t)s * (NKV * HD) + hh * HD;
        float v0 = x[lane], v1 = x[lane + 32], v2 = x[lane + 64], v3 = x[lane + 96];
        float ss = v0 * v0 + v1 * v1 + v2 * v2 + v3 * v3;
#pragma unroll
        for (int o = 16; o > 0; o >>= 1) ss += __shfl_xor_sync(0xFFFFFFFFu, ss, o);
        float inv = rsqrtf(ss * (1.f / HD) + 1e-6f);
        __half* y = vn + ((size_t)hh * S_LEN + s) * HD;   // row-major, coalesced
        y[lane]      = __float2half_rn(v0 * inv);
        y[lane + 32] = __float2half_rn(v1 * inv);
        y[lane + 64] = __float2half_rn(v2 * inv);
        y[lane + 96] = __float2half_rn(v3 * inv);
    }
}

// ---------------- causal GQA flash attention, fp16 MMA (round-11 exact) -----
#define ALDQ 136
#define OFF_QH 0
#define OFF_QL (128 * ALDQ)
#define OFF_KH0 (2 * 128 * ALDQ)
#define OFF_KL0 (OFF_KH0 + 64 * ALDQ)
#define OFF_KH1 (OFF_KL0 + 64 * ALDQ)
#define OFF_KL1 (OFF_KH1 + 64 * ALDQ)
#define OFF_VS0 (OFF_KL1 + 64 * ALDQ)
#define OFF_VS1 (OFF_VS0 + 64 * ALDQ)
#define HALVES_TOT (OFF_VS1 + 64 * ALDQ)
#define ATTN_SMEM_BYTES (HALVES_TOT * 2)

__global__ void __launch_bounds__(256) attn_fp16_kernel(
    const __half* __restrict__ Qh_g, const __half* __restrict__ Ql_g,
    const __half* __restrict__ Kh_g, const __half* __restrict__ Kl_g,
    const __half* __restrict__ V_g,
    __half* __restrict__ AOh)
{
    extern __shared__ __half sm[];
    __half* Qh = sm + OFF_QH;
    __half* Ql = sm + OFF_QL;
    uint32_t su = (uint32_t)__cvta_generic_to_shared(sm);
    const uint32_t uKH[2] = {su + OFF_KH0 * 2, su + OFF_KH1 * 2};
    const uint32_t uKL[2] = {su + OFF_KL0 * 2, su + OFF_KL1 * 2};
    const uint32_t uVS[2] = {su + OFF_VS0 * 2, su + OFF_VS1 * 2};

    const int hq = blockIdx.x;
    const int rb = (gridDim.y - 1) - blockIdx.y;   // heavy blocks first
    const int kvh = hq >> 2;
    const int tid = threadIdx.x, w = tid >> 5, lane = tid & 31;
    const int g = lane >> 2, t4 = lane & 3;
    const int m0 = 16 * w;
    const int la7 = lane & 7, lb = (lane >> 3) & 1, lc = (lane >> 4) & 1;

    const uint32_t offQA = ((uint32_t)(m0 + la7 + lb * 8) * ALDQ + lc * 8) * 2;
    const uint32_t offKB = ((uint32_t)(lc * 8 + la7) * ALDQ + lb * 8) * 2;
    const uint32_t offVB = ((uint32_t)(lb * 8 + la7) * ALDQ + lc * 8) * 2;

    const __half* Qg_h = Qh_g + ((size_t)hq * S_LEN + rb * 128) * HD;
    const __half* Qg_l = Ql_g + ((size_t)hq * S_LEN + rb * 128) * HD;
    const __half* Kg_h = Kh_g + (size_t)kvh * S_LEN * HD;
    const __half* Kg_l = Kl_g + (size_t)kvh * S_LEN * HD;
    const __half* Vg   = V_g  + (size_t)kvh * S_LEN * HD;

    auto issueKV = [&](int kb) {
        int st = kb & 1;
#pragma unroll
        for (int j = 0; j < 4; j++) {
            int c = tid + j * 256;            // 0..1023
            int row = c >> 4, seg = c & 15;
            size_t go = (size_t)(kb * 64 + row) * HD + seg * 8;
            uint32_t so = (uint32_t)(row * ALDQ + seg * 8) * 2;
            cp16(uKH[st] + so, Kg_h + go);
            cp16(uKL[st] + so, Kg_l + go);
            cp16(uVS[st] + so, Vg + go);
        }
    };

    issueKV(0); cp_commit();

    // Q tiles hi/lo (plain loads, overlap with cp.async)
#pragma unroll
    for (int j = 0; j < 8; j++) {
        int c = tid + j * 256;
        int row = c >> 4, seg = c & 15;
        *(uint4*)&Qh[row * ALDQ + seg * 8] =
            *(const uint4*)(Qg_h + (size_t)row * HD + seg * 8);
        *(uint4*)&Ql[row * ALDQ + seg * 8] =
            *(const uint4*)(Qg_l + (size_t)row * HD + seg * 8);
    }

    float mL = -INFINITY, mH = -INFINITY, lLs = 0.f, lHs = 0.f;
    float oacc[16][4];
#pragma unroll
    for (int nt = 0; nt < 16; nt++)
#pragma unroll
        for (int r = 0; r < 4; r++) oacc[nt][r] = 0.f;

    const int kbmax = 2 * rb + 1;
    for (int kb = 0; kb <= kbmax; kb++) {
        const int st = kb & 1;
        cp_wait<0>();
        __syncthreads();   // tile kb resident; all warps done reading st^1
        if (kb + 1 <= kbmax) { issueKV(kb + 1); cp_commit(); }

        // warps whose rows are entirely above the diagonal tile: skip
        if (kb == kbmax && m0 + 15 < 64) continue;

        // ---- S = Q K^T (fp16x3): 16 rows x 64 cols per warp ----
        float sacc[8][4];
#pragma unroll
        for (int nt = 0; nt < 8; nt++)
#pragma unroll
            for (int r = 0; r < 4; r++) sacc[nt][r] = 0.f;

#pragma unroll
        for (int ks = 0; ks < 8; ks++) {
            uint32_t ah[4], al[4];
            uint32_t oq = offQA + (uint32_t)(ks * 16) * 2;
            ldsm4(ah, su + OFF_QH * 2 + oq);
            ldsm4(al, su + OFF_QL * 2 + oq);
#pragma unroll
            for (int p = 0; p < 4; p++) {
                uint32_t bh4[4], bl4[4];
                uint32_t o = offKB + (uint32_t)(p * 16 * ALDQ + ks * 16) * 2;
                ldsm4(bh4, uKH[st] + o);
                ldsm4(bl4, uKL[st] + o);
#pragma unroll
                for (int q = 0; q < 2; q++) {
                    int nt = p * 2 + q;
                    uint32_t bh2[2] = {bh4[q * 2], bh4[q * 2 + 1]};
                    uint32_t bl2[2] = {bl4[q * 2], bl4[q * 2 + 1]};
                    mma16(sacc[nt], ah, bh2);
                    mma16(sacc[nt], ah, bl2);
                    mma16(sacc[nt], al, bh2);
                }
            }
        }

        // ---- causal mask ----
        if (kb >= 2 * rb) {
            int r0 = rb * 128 + m0 + g, r1 = r0 + 8;
#pragma unroll
            for (int nt = 0; nt < 8; nt++) {
                int c0 = kb * 64 + nt * 8 + 2 * t4;
                if (c0 > r0)     sacc[nt][0] = -INFINITY;
                if (c0 + 1 > r0) sacc[nt][1] = -INFINITY;
                if (c0 > r1)     sacc[nt][2] = -INFINITY;
                if (c0 + 1 > r1) sacc[nt][3] = -INFINITY;
            }
        }

        // ---- warp-local online softmax ----
        float rmL = -INFINITY, rmH = -INFINITY;
#pragma unroll
        for (int nt = 0; nt < 8; nt++) {
            rmL = fmaxf(rmL, fmaxf(sacc[nt][0], sacc[nt][1]));
            rmH = fmaxf(rmH, fmaxf(sacc[nt][2], sacc[nt][3]));
        }
        rmL = fmaxf(rmL, __shfl_xor_sync(0xFFFFFFFFu, rmL, 1));
        rmL = fmaxf(rmL, __shfl_xor_sync(0xFFFFFFFFu, rmL, 2));
        rmH = fmaxf(rmH, __shfl_xor_sync(0xFFFFFFFFu, rmH, 1));
        rmH = fmaxf(rmH, __shfl_xor_sync(0xFFFFFFFFu, rmH, 2));
        float mnL = fmaxf(mL, rmL), mnH = fmaxf(mH, rmH);
        float aL = __expf(mL - mnL), aH = __expf(mH - mnH);
        mL = mnL; mH = mnH;

        uint32_t pfL[8], pfH[8];
        float lsL = 0.f, lsH = 0.f;
#pragma unroll
        for (int nt = 0; nt < 8; nt++) {
            float p0 = __expf(sacc[nt][0] - mnL);
            float p1 = __expf(sacc[nt][1] - mnL);
            float p2 = __expf(sacc[nt][2] - mnH);
            float p3 = __expf(sacc[nt][3] - mnH);
            lsL += p0 + p1; lsH += p2 + p3;
            pfL[nt] = pack2(p0, p1);
            pfH[nt] = pack2(p2, p3);
        }
        lsL += __shfl_xor_sync(0xFFFFFFFFu, lsL, 1);
        lsL += __shfl_xor_sync(0xFFFFFFFFu, lsL, 2);
        lsH += __shfl_xor_sync(0xFFFFFFFFu, lsH, 1);
        lsH += __shfl_xor_sync(0xFFFFFFFFu, lsH, 2);
        lLs = lLs * aL + lsL;
        lHs = lHs * aH + lsH;

#pragma unroll
        for (int nt = 0; nt < 16; nt++) {
            oacc[nt][0] *= aL; oacc[nt][1] *= aL;
            oacc[nt][2] *= aH; oacc[nt][3] *= aH;
        }

        // ---- O += P @ V (P from registers; V row-major via ldsm.trans) ----
#pragma unroll
        for (int ks = 0; ks < 4; ks++) {
            uint32_t pa[4] = {pfL[2 * ks], pfH[2 * ks], pfL[2 * ks + 1], pfH[2 * ks + 1]};
#pragma unroll
            for (int p = 0; p < 8; p++) {
                uint32_t vb4[4];
                uint32_t o = offVB + (uint32_t)(ks * 16 * ALDQ + p * 16) * 2;
                ldsm4t(vb4, uVS[st] + o);
                uint32_t b0[2] = {vb4[0], vb4[1]};
                uint32_t b1[2] = {vb4[2], vb4[3]};
                mma16(oacc[2 * p],     pa, b0);
                mma16(oacc[2 * p + 1], pa, b1);
            }
        }
    }

    // ---- epilogue: normalize, fp16 convert (hi only), store AO [s][hid] ----
    float invL = 1.f / lLs, invH = 1.f / lHs;
    size_t sL = (size_t)(rb * 128 + m0 + g) * HIDDEN;
    size_t sH = (size_t)(rb * 128 + m0 + g + 8) * HIDDEN;
#pragma unroll
    for (int nt = 0; nt < 16; nt++) {
        int col = hq * HD + nt * 8 + 2 * t4;
        *(__half2*)&AOh[sL + col] = __halves2half2(
            __float2half_rn(oacc[nt][0] * invL), __float2half_rn(oacc[nt][1] * invL));
        *(__half2*)&AOh[sH + col] = __halves2half2(
            __float2half_rn(oacc[nt][2] * invH), __float2half_rn(oacc[nt][3] * invH));
    }
}

// ---------------------------------------------------------------------------
extern "C" void kernel_launch(void* const* d_in, const int* in_sizes, int n_in,
                              void* d_out, int out_size)
{
    const float* hs   = (const float*)d_in[0];
    const float* cosT = (const float*)d_in[1];
    const float* sinT = (const float*)d_in[2];
    // d_in[3] = attention_mask: pure causal, implemented directly (not read)
    const float* Wq = (const float*)d_in[4];
    const float* Wk = (const float*)d_in[5];
    const float* Wv = (const float*)d_in[6];
    const float* Wo = (const float*)d_in[7];
    const float* qw = (const float*)d_in[8];
    const float* kw = (const float*)d_in[9];
    float* out = (float*)d_out;

    float *qraw, *kraw, *vraw;
    __half *hsH, *hsL, *wqH, *wqL, *wkH, *wkL, *wvH, *wvL, *woH, *woL;
    __half *qnH, *qnL, *knH, *knL, *vn, *aoH;
    cudaGetSymbolAddress((void**)&qraw, g_Qraw);
    cudaGetSymbolAddress((void**)&kraw, g_Kraw);
    cudaGetSymbolAddress((void**)&vraw, g_Vraw);
    cudaGetSymbolAddress((void**)&hsH, g_hsH); cudaGetSymbolAddress((void**)&hsL, g_hsL);
    cudaGetSymbolAddress((void**)&wqH, g_WqH); cudaGetSymbolAddress((void**)&wqL, g_WqL);
    cudaGetSymbolAddress((void**)&wkH, g_WkH); cudaGetSymbolAddress((void**)&wkL, g_WkL);
    cudaGetSymbolAddress((void**)&wvH, g_WvH); cudaGetSymbolAddress((void**)&wvL, g_WvL);
    cudaGetSymbolAddress((void**)&woH, g_WoH); cudaGetSymbolAddress((void**)&woL, g_WoL);
    cudaGetSymbolAddress((void**)&qnH, g_QnH); cudaGetSymbolAddress((void**)&qnL, g_QnL);
    cudaGetSymbolAddress((void**)&knH, g_KnH); cudaGetSymbolAddress((void**)&knL, g_KnL);
    cudaGetSymbolAddress((void**)&vn, g_Vn);
    cudaGetSymbolAddress((void**)&aoH, g_AOH);

    cudaFuncSetAttribute(qkv_gemm_kernel,
                         cudaFuncAttributeMaxDynamicSharedMemorySize, GEMM3_SMEM_BYTES);
    cudaFuncSetAttribute(gemm_fp16x2,
                         cudaFuncAttributeMaxDynamicSharedMemorySize, GEMM2_SMEM_BYTES);
    cudaFuncSetAttribute(attn_fp16_kernel,
                         cudaFuncAttributeMaxDynamicSharedMemorySize, ATTN_SMEM_BYTES);

    // split inputs to fp16 hi/lo (single fused launch)
    {
        SplitJob j0 = {hs, hsH, hsL, S_LEN * HIDDEN / 4};
        SplitJob j1 = {Wq, wqH, wqL, HIDDEN * HIDDEN / 4};
        SplitJob j2 = {Wk, wkH, wkL, NKV * HD * HIDDEN / 4};
        SplitJob j3 = {Wv, wvH, wvL, NKV * HD * HIDDEN / 4};
        SplitJob j4 = {Wo, woH, woL, HIDDEN * HIDDEN / 4};
        int tot = j0.n4 + j1.n4 + j2.n4 + j3.n4 + j4.n4;
        split_all_kernel<<<(tot + 255) / 256, 256>>>(j0, j1, j2, j3, j4);
    }

    // fused QKV projections (Q,K: fp16x3; V: fp16x2)
    qkv_gemm_kernel<<<dim3(24, S_LEN / 128), 256, GEMM3_SMEM_BYTES>>>(
        hsH, hsL, wqH, wqL, wkH, wkL, wvH, wvL, qraw, kraw, vraw);

    // fused RMSNorm (+RoPE): Q hi/lo, K hi/lo, V row-major fp16
    {
        int tasks = S_LEN * (NH + NKV + NKV);
        norm_all_kernel<<<(tasks + 3) / 4, 128>>>(
            qraw, kraw, vraw, qnH, qnL, knH, knL, vn, qw, kw, cosT, sinT);
    }

    // attention (round-11 structure, unchanged)
    attn_fp16_kernel<<<dim3(NH, S_LEN / 128), 256, ATTN_SMEM_BYTES>>>(
        qnH, qnL, knH, knL, vn, aoH);

    // output projection (fp16x2: A = attention output hi-only)
    gemm_fp16x2<<<dim3(HIDDEN / 128, S_LEN / 128), 256, GEMM2_SMEM_BYTES>>>(
        aoH, woH, woL, out, S_LEN, HIDDEN, HIDDEN);
}